// round 17
// baseline (speedup 1.0000x reference)
#include <cuda_runtime.h>

// SEIR scan — single fused kernel, warp-specialized stores.
// Output layout: [4, T, B] — planes S, E, I, R.
//
// 128 blocks x 128 threads. Warps 0-1 (tid 0-63): compute — each thread owns
// one channel, scans all T steps, writes states to a double-buffered smem
// window (STS.32, cheap). Warps 2-3 (tid 64-127): storers — drain each
// 32-step window to global with LDS.128 + STG.128 evict-first stores, on the
// otherwise-idle SMSPs. X is staged through a 4-deep cp.async pipeline.
// Traffic = X once (64MB) + output once (256MB).

#define WSTEP  32          // steps per window
#define XBUF   4           // X pipeline depth (windows)
#define CPB    64          // channels per block

// ---- cp.async helpers ----
__device__ __forceinline__ void cp_async16(void* smem_dst, const void* gsrc)
{
    unsigned s = (unsigned)__cvta_generic_to_shared(smem_dst);
    asm volatile("cp.async.cg.shared.global [%0], [%1], 16;"
                 :: "r"(s), "l"(gsrc));
}
#define CP_COMMIT() asm volatile("cp.async.commit_group;" ::: "memory")
#define CP_WAIT3()  asm volatile("cp.async.wait_group 3;"  ::: "memory")

// 10-op SEIR step; invN folded into wbN.
//   a = (wbN*I)*S ; b = ws*E ; c = wg*I
//   S' = S - x*a ; E' = E + x*(a-b) ; I' = I + x*(b-c) ; R' = R + x*c
__device__ __forceinline__ void seir_step10(float x, float wbN, float wg, float ws,
                                            float& S, float& E, float& I, float& R)
{
    const float a  = (wbN * I) * S;
    const float b  = ws * E;
    const float c  = wg * I;
    const float ab = a - b;
    const float bc = b - c;
    S = fmaf(-x, a, S);
    E = fmaf(x, ab, E);
    I = fmaf(x, bc, I);
    R = fmaf(x, c, R);
}

// ---------------------------------------------------------------- fused
template<int B_>
__global__ __launch_bounds__(128, 1)
void seir_fused(const float* __restrict__ X,
                const float* __restrict__ w_beta,
                const float* __restrict__ w_gamma,
                const float* __restrict__ w_sigma,
                const float* __restrict__ S0,
                const float* __restrict__ I0,
                const float* __restrict__ R0,
                const float* __restrict__ Nvec,
                float* __restrict__ out,
                int T)
{
    // dynamic smem: xs[XBUF][WSTEP][CPB] (32KB) + sb[2][WSTEP][4][CPB] (64KB)
    extern __shared__ __align__(16) float smem[];
    float* xs = smem;                                  // XBUF*WSTEP*CPB
    float* sb = smem + XBUF * WSTEP * CPB;             // 2*WSTEP*4*CPB

    const int tid   = threadIdx.x;
    const int col0  = blockIdx.x * CPB;
    const int ch    = col0 + (tid & 63);
    const bool isComp = (tid < 64);

    const int NS  = T - 1;
    const int Tm1 = T - 1;
    const size_t TB = (size_t)T * (size_t)B_;

    float S = 0.f, E = 0.f, I = 0.f, R = 0.f;
    float wbN = 0.f, wg = 0.f, ws = 0.f;
    if (isComp) {
        const float invN = 1.0f / Nvec[ch];
        wbN = w_beta[ch] * invN;
        wg  = w_gamma[ch];
        ws  = w_sigma[ch];
        S = S0[ch]; E = 0.0f; I = I0[ch]; R = R0[ch];
        // row 0 = initial state
        __stcs(out + ch, S);
        __stcs(out + TB + ch, E);
        __stcs(out + 2 * TB + ch, I);
        __stcs(out + 3 * TB + ch, R);
    }
    if (NS <= 0) return;

    const int W = (NS + WSTEP - 1) / WSTEP;

    // issue X loads for window wi into xs[wi%XBUF]; ALWAYS commits a group
    // (possibly empty) so wait_group counting stays aligned.
    auto issue_win = [&](int wi) {
        if (wi < W) {
            float* dst = xs + (size_t)(wi & (XBUF - 1)) * WSTEP * CPB;
#pragma unroll
            for (int c = 0; c < (WSTEP * 16) / 128; ++c) {
                const int cc   = tid + c * 128;
                const int row  = cc >> 4;
                const int off  = (cc & 15) * 4;
                const int trow = min(wi * WSTEP + row, Tm1);  // clamp: valid
                cp_async16(dst + row * CPB + off,
                           X + (size_t)trow * B_ + col0 + off);
            }
        }
        CP_COMMIT();
    };

    issue_win(0); issue_win(1); issue_win(2); issue_win(3);

    // drain window wd (kc valid steps) to global
    auto drain = [&](int wd, int kc) {
        const int stid = tid - 64;
        const float* buf = sb + (size_t)(wd & 1) * WSTEP * 4 * CPB;
        for (int c = stid; c < kc * 64; c += 64) {    // kc*4 combos * 16 chunks
            const int combo = c >> 4;
            const int l16   = c & 15;
            const int k     = combo >> 2;
            const int plane = combo & 3;
            const float4 v = *(const float4*)(buf + (k * 4 + plane) * CPB + l16 * 4);
            __stcs((float4*)(out + (size_t)plane * TB
                             + (size_t)(wd * WSTEP + k + 1) * B_
                             + col0 + l16 * 4), v);
        }
    };

    for (int w = 0; w < W; ++w) {
        CP_WAIT3();              // window w's X loads complete
        __syncthreads();         // + sb[w&1] fully drained (done at w-1)

        if (isComp) {
            const float* xp = xs + (size_t)(w & (XBUF - 1)) * WSTEP * CPB + tid;
            float* sp = sb + (size_t)(w & 1) * WSTEP * 4 * CPB + tid;
            const int kc = min(WSTEP, NS - w * WSTEP);
            if (kc == WSTEP) {
#pragma unroll
                for (int k = 0; k < WSTEP; ++k) {
                    const float x = xp[k * CPB];
                    seir_step10(x, wbN, wg, ws, S, E, I, R);
                    float* row = sp + k * 4 * CPB;
                    row[0 * CPB] = S;
                    row[1 * CPB] = E;
                    row[2 * CPB] = I;
                    row[3 * CPB] = R;
                }
            } else {
                for (int k = 0; k < kc; ++k) {
                    const float x = xp[k * CPB];
                    seir_step10(x, wbN, wg, ws, S, E, I, R);
                    float* row = sp + k * 4 * CPB;
                    row[0 * CPB] = S;
                    row[1 * CPB] = E;
                    row[2 * CPB] = I;
                    row[3 * CPB] = R;
                }
            }
        } else if (w > 0) {
            drain(w - 1, WSTEP);     // windows before the last are full
        }

        __syncthreads();         // sb[w&1] full; xs[w%XBUF] consumed
        issue_win(w + XBUF);
    }

    // final drain (storer warps only; no further syncs needed)
    if (!isComp) {
        const int kc = NS - (W - 1) * WSTEP;
        drain(W - 1, kc);
    }
}

// ------------------------------------------------ fallback (shape safety)
__global__ void seir_fallback(const float* __restrict__ X,
                              const float* __restrict__ w_beta,
                              const float* __restrict__ w_gamma,
                              const float* __restrict__ w_sigma,
                              const float* __restrict__ S0,
                              const float* __restrict__ I0,
                              const float* __restrict__ R0,
                              const float* __restrict__ Nvec,
                              float* __restrict__ out, int T, int B)
{
    const int b = blockIdx.x * blockDim.x + threadIdx.x;
    if (b >= B) return;
    const float invN = 1.0f / Nvec[b];
    const float wbN = w_beta[b] * invN;
    const float wg = w_gamma[b], ws = w_sigma[b];
    float S = S0[b], E = 0.0f, I = I0[b], R = R0[b];
    const size_t TB = (size_t)T * B;
    out[b] = S; out[TB + b] = E; out[2 * TB + b] = I; out[3 * TB + b] = R;
    for (int t = 0; t < T - 1; ++t) {
        const float x = X[(size_t)t * B + b];
        seir_step10(x, wbN, wg, ws, S, E, I, R);
        const size_t r = (size_t)(t + 1) * B + b;
        out[r] = S; out[TB + r] = E; out[2 * TB + r] = I; out[3 * TB + r] = R;
    }
}

extern "C" void kernel_launch(void* const* d_in, const int* in_sizes, int n_in,
                              void* d_out, int out_size)
{
    const float* X      = (const float*)d_in[0];
    const float* w_beta = (const float*)d_in[1];
    const float* w_gamma= (const float*)d_in[2];
    const float* w_sigma= (const float*)d_in[3];
    const float* S0     = (const float*)d_in[4];
    const float* I0     = (const float*)d_in[5];
    const float* R0     = (const float*)d_in[6];
    const float* Nvec   = (const float*)d_in[7];
    float* out = (float*)d_out;

    const int B = in_sizes[1];         // w_beta is [B]
    const int T = in_sizes[0] / B;     // X is [T, B]

    if (B == 8192 && T >= 2) {
        const int smem = (XBUF * WSTEP * CPB + 2 * WSTEP * 4 * CPB)
                         * (int)sizeof(float);                    // 96 KB
        cudaFuncSetAttribute(seir_fused<8192>,
                             cudaFuncAttributeMaxDynamicSharedMemorySize, smem);
        seir_fused<8192><<<8192 / CPB, 128, smem>>>(X, w_beta, w_gamma,
                                                    w_sigma, S0, I0, R0,
                                                    Nvec, out, T);
    } else {
        seir_fallback<<<(B + 127) / 128, 128>>>(X, w_beta, w_gamma, w_sigma,
                                                S0, I0, R0, Nvec, out, T, B);
    }
}